// round 14
// baseline (speedup 1.0000x reference)
#include <cuda_runtime.h>
#include <cuda_bf16.h>
#include <cstdint>

#define TSEQ  512
#define BATCH 128
#define HID   1024
#define NLAY  4
#define BH    (BATCH*HID)
#define KTOT  2048              // K = concat(cur, hprev)
#define KC    128               // K per chunk (2 sub-tiles of 64 cols)
#define NCH   (KTOT/KC)         // 16 chunks
#define SUBB  8192              // 64 rows x 128 B sub-tile
#define TILEB (2*SUBB)          // one operand tile per chunk: 16 KB
#define STAGEB (4*TILEB)        // Ah, Al, Wh, Wl = 64 KB / stage
#define STAGES 3
#define DYN_SMEM (STAGES*STAGEB + 256)   // 192 KB (also hosts the 48 KB reduction scratch)

// ---------------- static device buffers ----------------
__device__ __align__(256) __nv_bfloat16 g_xhi[(size_t)TSEQ*BH];
__device__ __align__(256) __nv_bfloat16 g_xlo[(size_t)TSEQ*BH];
__device__ __align__(256) __nv_bfloat16 g_rhi[NLAY*2*BH];             // hidden ring hi [layer][t&1]
__device__ __align__(256) __nv_bfloat16 g_rlo[NLAY*2*BH];             // hidden ring lo
__device__ __align__(256) __nv_bfloat16 g_whi[(size_t)NLAY*HID*KTOT]; // Wcat=[W_ih;W_hh] hi, K-major
__device__ __align__(256) __nv_bfloat16 g_wlo[(size_t)NLAY*HID*KTOT];

// ---------------- PTX helpers (baseline sm_80-level: safe on compute_103) -----
__device__ __forceinline__ unsigned smem_u32(const void* p) {
    unsigned a;
    asm("{ .reg .u64 t; cvta.to.shared.u64 t, %1; cvt.u32.u64 %0, t; }" : "=r"(a) : "l"(p));
    return a;
}
__device__ __forceinline__ void cp_async16(unsigned s, const void* g) {
    asm volatile("cp.async.ca.shared.global [%0], [%1], 16;\n" :: "r"(s), "l"(g));
}
__device__ __forceinline__ void cp_commit() { asm volatile("cp.async.commit_group;\n" ::: "memory"); }
template<int N>
__device__ __forceinline__ void cp_wait() { asm volatile("cp.async.wait_group %0;\n" :: "n"(N) : "memory"); }

__device__ __forceinline__ void ldsm4(unsigned& r0, unsigned& r1, unsigned& r2, unsigned& r3, unsigned a) {
    asm volatile("ldmatrix.sync.aligned.m8n8.x4.shared.b16 {%0,%1,%2,%3}, [%4];"
                 : "=r"(r0), "=r"(r1), "=r"(r2), "=r"(r3) : "r"(a));
}
__device__ __forceinline__ void mma16816(float4& c, const unsigned* a, unsigned b0, unsigned b1) {
    asm volatile("mma.sync.aligned.m16n8k16.row.col.f32.bf16.bf16.f32 "
                 "{%0,%1,%2,%3}, {%4,%5,%6,%7}, {%8,%9}, {%0,%1,%2,%3};"
                 : "+f"(c.x), "+f"(c.y), "+f"(c.z), "+f"(c.w)
                 : "r"(a[0]), "r"(a[1]), "r"(a[2]), "r"(a[3]), "r"(b0), "r"(b1));
}

// ---------------- split-fp32 conversion kernels ----------------
__global__ void conv_x(const float* __restrict__ x) {
    size_t i = (size_t)blockIdx.x * blockDim.x + threadIdx.x;
    if (i >= (size_t)TSEQ * BH) return;
    float v = x[i];
    __nv_bfloat16 h = __float2bfloat16(v);
    g_xhi[i] = h;
    g_xlo[i] = __float2bfloat16(v - __bfloat162float(h));
}
__global__ void conv_w(const float* __restrict__ Wih, const float* __restrict__ Whh) {
    size_t i = (size_t)blockIdx.x * blockDim.x + threadIdx.x;
    if (i >= (size_t)NLAY * HID * KTOT) return;
    int k = (int)(i & (KTOT - 1));
    size_t ln = i >> 11;                          // layer*HID + n
    float v = (k < HID) ? Wih[ln * HID + k] : Whh[ln * HID + (k - HID)];
    __nv_bfloat16 h = __float2bfloat16(v);
    g_whi[i] = h;
    g_wlo[i] = __float2bfloat16(v - __bfloat162float(h));
}

// ---------------- wavefront kernel ----------------
// 512 threads = 16 warps: group g = wid>>2 takes kk = g (mod 4) within each chunk;
// quadrant p = wid&3 is the 32x32 warp tile of the 64x64 CTA tile.
// 4 warps/SMSP hide latency at CONSTANT crossbar bytes/MMA; partials reduced in smem.
__global__ void __launch_bounds__(512, 1)
rnn_wave_mma(int s, const float* __restrict__ bih, const float* __restrict__ bhh,
             float* __restrict__ out)
{
    const int layer = blockIdx.y;
    const int t = s - layer;
    if (t < 0 || t >= TSEQ) return;

    const int mt = blockIdx.x >> 4;        // 0..1
    const int nt = blockIdx.x & 15;        // 0..15
    const int m0 = mt * 64;
    const int n0 = nt * 64;

    extern __shared__ __align__(16) char dynsm[];
    const unsigned dbase = (smem_u32(dynsm) + 127) & ~127u;

    const int tid  = threadIdx.x;
    const int wid  = tid >> 5;
    const int lane = tid & 31;
    const int grp  = wid >> 2;             // 0..3: kk residue class
    const int p    = wid & 3;              // quadrant
    const int wm   = p >> 1;               // warp M offset 32*wm
    const int wn   = p & 1;                // warp N offset 32*wn

    // ---- source pointers ----
    const __nv_bfloat16* curhi = (layer == 0) ? g_xhi + (size_t)t * BH
                                              : g_rhi + (size_t)((layer-1)*2 + (t & 1)) * BH;
    const __nv_bfloat16* curlo = (layer == 0) ? g_xlo + (size_t)t * BH
                                              : g_rlo + (size_t)((layer-1)*2 + (t & 1)) * BH;
    const __nv_bfloat16* phi = g_rhi + (size_t)(layer*2 + ((t-1) & 1)) * BH;
    const __nv_bfloat16* plo = g_rlo + (size_t)(layer*2 + ((t-1) & 1)) * BH;
    const __nv_bfloat16* whi = g_whi + (size_t)layer * HID * KTOT;
    const __nv_bfloat16* wlo = g_wlo + (size_t)layer * HID * KTOT;

    const int nChunks = (t == 0) ? (NCH / 2) : NCH;   // KC=128 divides HID: no straddle

    // ---- producer: 512 threads -> 1 granule per (operand, sub-tile): 8 cp.async/thread ----
    const int prow = tid >> 3;             // 0..63
    const int pg   = tid & 7;
    const unsigned so = (unsigned)(prow*128 + ((pg ^ (prow & 7)) << 4));

    auto issue_chunk = [&](int c, int buf) {
        const unsigned sb = dbase + buf * STAGEB;
        const int k0 = c * KC;
        const __nv_bfloat16 *ah, *al; int koff;
        if (k0 < HID) { ah = curhi; al = curlo; koff = k0; }
        else          { ah = phi;   al = plo;   koff = k0 - HID; }
        #pragma unroll
        for (int sub = 0; sub < 2; sub++) {
            const unsigned ss = sb + sub * SUBB;
            const int ks = koff + sub * 64;
            const int kw = k0 + sub * 64;
            cp_async16(ss + 0*TILEB + so, ah  + (size_t)(m0+prow)*HID + ks + pg*8);
            cp_async16(ss + 1*TILEB + so, al  + (size_t)(m0+prow)*HID + ks + pg*8);
            cp_async16(ss + 2*TILEB + so, whi + (size_t)(n0+prow)*KTOT + kw + pg*8);
            cp_async16(ss + 3*TILEB + so, wlo + (size_t)(n0+prow)*KTOT + kw + pg*8);
        }
        cp_commit();
    };

    // ---- ldmatrix lane addressing ----
    const int x7 = lane & 7;
    const int asel = lane >> 4;
    const unsigned aRowOff0 = (unsigned)((wm*32 +      (lane & 15)) * 128);
    const unsigned aRowOff1 = (unsigned)((wm*32 + 16 + (lane & 15)) * 128);
    const int brow_in = (lane & 7) + ((lane & 16) >> 1);
    const int bsel = (lane >> 3) & 1;
    const unsigned bRowOff0 = (unsigned)((wn*32 +      brow_in) * 128);
    const unsigned bRowOff1 = (unsigned)((wn*32 + 16 + brow_in) * 128);

    float4 acc[2][4];
    #pragma unroll
    for (int mi = 0; mi < 2; mi++)
        #pragma unroll
        for (int nf = 0; nf < 4; nf++) acc[mi][nf] = make_float4(0.f, 0.f, 0.f, 0.f);

    // one k16 step: 8 LDSM + 24 MMA (group's own kk only -> 2 steps per chunk)
    auto k16_step = [&](unsigned sb, int kk) {
        const unsigned ss = sb + (unsigned)(kk >> 2) * SUBB;
        const int ki = kk & 3;
        const unsigned axor = (unsigned)(((ki*2 + asel) ^ x7) << 4);
        const unsigned bxor = (unsigned)(((ki*2 + bsel) ^ x7) << 4);
        unsigned ah[2][4], al[2][4], wh[2][4], wl[2][4];
        ldsm4(ah[0][0], ah[0][1], ah[0][2], ah[0][3], ss + 0*TILEB + aRowOff0 + axor);
        ldsm4(ah[1][0], ah[1][1], ah[1][2], ah[1][3], ss + 0*TILEB + aRowOff1 + axor);
        ldsm4(al[0][0], al[0][1], al[0][2], al[0][3], ss + 1*TILEB + aRowOff0 + axor);
        ldsm4(al[1][0], al[1][1], al[1][2], al[1][3], ss + 1*TILEB + aRowOff1 + axor);
        ldsm4(wh[0][0], wh[0][1], wh[0][2], wh[0][3], ss + 2*TILEB + bRowOff0 + bxor);
        ldsm4(wh[1][0], wh[1][1], wh[1][2], wh[1][3], ss + 2*TILEB + bRowOff1 + bxor);
        ldsm4(wl[0][0], wl[0][1], wl[0][2], wl[0][3], ss + 3*TILEB + bRowOff0 + bxor);
        ldsm4(wl[1][0], wl[1][1], wl[1][2], wl[1][3], ss + 3*TILEB + bRowOff1 + bxor);
        #pragma unroll
        for (int mi = 0; mi < 2; mi++)     // pass 1: hi*hi
            #pragma unroll
            for (int nf = 0; nf < 4; nf++)
                mma16816(acc[mi][nf], ah[mi], wh[nf>>1][(nf&1)*2], wh[nf>>1][(nf&1)*2+1]);
        #pragma unroll
        for (int mi = 0; mi < 2; mi++)     // pass 2: hi*lo
            #pragma unroll
            for (int nf = 0; nf < 4; nf++)
                mma16816(acc[mi][nf], ah[mi], wl[nf>>1][(nf&1)*2], wl[nf>>1][(nf&1)*2+1]);
        #pragma unroll
        for (int mi = 0; mi < 2; mi++)     // pass 3: lo*hi
            #pragma unroll
            for (int nf = 0; nf < 4; nf++)
                mma16816(acc[mi][nf], al[mi], wh[nf>>1][(nf&1)*2], wh[nf>>1][(nf&1)*2+1]);
    };

    // ---- 3-stage pipeline, one barrier per chunk; each group computes its 2 kk ----
    issue_chunk(0, 0);
    issue_chunk(1, 1);
    for (int c = 0; c < nChunks; c++) {
        if (c + 1 < nChunks) cp_wait<1>();
        else                 cp_wait<0>();
        __syncthreads();                   // chunk c visible; stage (c+2)%3 free (compute c-1 done)
        if (c + 2 < nChunks) issue_chunk(c + 2, (c + 2) % STAGES);
        const unsigned sb = dbase + (c % STAGES) * STAGEB;
        k16_step(sb, grp);
        k16_step(sb, grp + 4);
    }

    // ---- cross-group reduction in smem (stages are dead now) ----
    __syncthreads();
    float4* red = (float4*)(dynsm + (dbase - smem_u32(dynsm)));
    // groups 1..3 store their partials: region (grp-1), slot = p*256 + frag*32 + lane
    if (grp > 0) {
        float4* r = red + (size_t)(grp - 1) * 1024;
        #pragma unroll
        for (int mi = 0; mi < 2; mi++)
            #pragma unroll
            for (int nf = 0; nf < 4; nf++)
                r[p*256 + (mi*4 + nf)*32 + lane] = acc[mi][nf];
    }
    __syncthreads();
    if (grp == 0) {
        #pragma unroll
        for (int gsrc = 0; gsrc < 3; gsrc++) {
            const float4* r = red + (size_t)gsrc * 1024;
            #pragma unroll
            for (int mi = 0; mi < 2; mi++)
                #pragma unroll
                for (int nf = 0; nf < 4; nf++) {
                    float4 v = r[p*256 + (mi*4 + nf)*32 + lane];
                    acc[mi][nf].x += v.x; acc[mi][nf].y += v.y;
                    acc[mi][nf].z += v.z; acc[mi][nf].w += v.w;
                }
        }

        // ---- epilogue (group 0 only): bias + tanh, split hi/lo, store ----
        const size_t rb = (size_t)(layer*2 + (t & 1)) * BH;
        #pragma unroll
        for (int mi = 0; mi < 2; mi++) {
            const int mlo = m0 + wm*32 + mi*16 + (lane >> 2);
            #pragma unroll
            for (int nf = 0; nf < 4; nf++) {
                const int n = n0 + wn*32 + nf*8 + (lane & 3)*2;
                const float b0 = bih[layer*HID + n]     + bhh[layer*HID + n];
                const float b1 = bih[layer*HID + n + 1] + bhh[layer*HID + n + 1];
                const float v00 = tanhf(acc[mi][nf].x + b0);
                const float v01 = tanhf(acc[mi][nf].y + b1);
                const float v10 = tanhf(acc[mi][nf].z + b0);
                const float v11 = tanhf(acc[mi][nf].w + b1);
                #pragma unroll
                for (int rh = 0; rh < 2; rh++) {
                    const int m = mlo + rh*8;
                    const float va = rh ? v10 : v00;
                    const float vb = rh ? v11 : v01;
                    const __nv_bfloat16 ha = __float2bfloat16(va);
                    const __nv_bfloat16 hb = __float2bfloat16(vb);
                    const __nv_bfloat16 la = __float2bfloat16(va - __bfloat162float(ha));
                    const __nv_bfloat16 lb = __float2bfloat16(vb - __bfloat162float(hb));
                    const unsigned hpack = (unsigned)__bfloat16_as_ushort(ha) |
                                           ((unsigned)__bfloat16_as_ushort(hb) << 16);
                    const unsigned lpack = (unsigned)__bfloat16_as_ushort(la) |
                                           ((unsigned)__bfloat16_as_ushort(lb) << 16);
                    *reinterpret_cast<unsigned*>(&g_rhi[rb + (size_t)m*HID + n]) = hpack;
                    *reinterpret_cast<unsigned*>(&g_rlo[rb + (size_t)m*HID + n]) = lpack;
                    if (layer == NLAY - 1) {
                        float2 o = make_float2(va, vb);
                        *reinterpret_cast<float2*>(&out[(size_t)t*BH + (size_t)m*HID + n]) = o;
                    }
                }
            }
        }
    }
}

extern "C" void kernel_launch(void* const* d_in, const int* in_sizes, int n_in,
                              void* d_out, int out_size) {
    const float* x   = (const float*)d_in[0];
    const float* Wih = (const float*)d_in[1];
    const float* Whh = (const float*)d_in[2];
    const float* bih = (const float*)d_in[3];
    const float* bhh = (const float*)d_in[4];
    float* out = (float*)d_out;

    cudaFuncSetAttribute(rnn_wave_mma, cudaFuncAttributeMaxDynamicSharedMemorySize, DYN_SMEM);

    // One-time (per replay) split fp32 -> bf16 hi/lo
    conv_x<<<(unsigned)(((size_t)TSEQ*BH + 255) / 256), 256>>>(x);
    conv_w<<<(unsigned)(((size_t)NLAY*HID*KTOT + 255) / 256), 256>>>(Wih, Whh);

    // Wavefront s = t + layer: 515 sequential launches; kernel boundaries = sync.
    const dim3 grid(32, NLAY);
    for (int s = 0; s < TSEQ + NLAY - 1; s++) {
        rnn_wave_mma<<<grid, 512, DYN_SMEM>>>(s, bih, bhh, out);
    }
}

// round 16
// speedup vs baseline: 2.5485x; 2.5485x over previous
#include <cuda_runtime.h>
#include <cuda_fp16.h>
#include <cstdint>

#define TSEQ  512
#define BATCH 128
#define HID   1024
#define NLAY  4
#define BH    (BATCH*HID)
#define KTOT  2048              // K = concat(cur, hprev)
#define KC    128               // K per chunk (2 sub-tiles of 64 k-cols x 128 B)
#define NCH   (KTOT/KC)         // 16 chunks
#define SUBB  8192              // 64 rows x 128 B sub-tile
#define TILEB (2*SUBB)          // one operand (A or W) per chunk: 16 KB
#define STAGEB (2*TILEB)        // A + W = 32 KB / stage
#define STAGES 5
#define DYN_SMEM (STAGES*STAGEB + 256)   // 160 KB

// ---------------- static device buffers ----------------
__device__ __align__(256) __half g_x16[(size_t)TSEQ*BH];              // x in fp16
__device__ __align__(256) __half g_r16[NLAY*2*BH];                    // hidden ring [layer][t&1]
__device__ __align__(256) __half g_w16[(size_t)NLAY*HID*KTOT];        // Wcat=[W_ih;W_hh], K-major

// ---------------- PTX helpers (baseline sm_80-level: safe on compute_103) -----
__device__ __forceinline__ unsigned smem_u32(const void* p) {
    unsigned a;
    asm("{ .reg .u64 t; cvta.to.shared.u64 t, %1; cvt.u32.u64 %0, t; }" : "=r"(a) : "l"(p));
    return a;
}
__device__ __forceinline__ void cp_async16(unsigned s, const void* g) {
    asm volatile("cp.async.cg.shared.global [%0], [%1], 16;\n" :: "r"(s), "l"(g));
}
__device__ __forceinline__ void cp_commit() { asm volatile("cp.async.commit_group;\n" ::: "memory"); }
template<int N>
__device__ __forceinline__ void cp_wait() { asm volatile("cp.async.wait_group %0;\n" :: "n"(N) : "memory"); }

__device__ __forceinline__ void ldsm4(unsigned& r0, unsigned& r1, unsigned& r2, unsigned& r3, unsigned a) {
    asm volatile("ldmatrix.sync.aligned.m8n8.x4.shared.b16 {%0,%1,%2,%3}, [%4];"
                 : "=r"(r0), "=r"(r1), "=r"(r2), "=r"(r3) : "r"(a));
}
__device__ __forceinline__ void mma16816(float4& c, const unsigned* a, unsigned b0, unsigned b1) {
    asm volatile("mma.sync.aligned.m16n8k16.row.col.f32.f16.f16.f32 "
                 "{%0,%1,%2,%3}, {%4,%5,%6,%7}, {%8,%9}, {%0,%1,%2,%3};"
                 : "+f"(c.x), "+f"(c.y), "+f"(c.z), "+f"(c.w)
                 : "r"(a[0]), "r"(a[1]), "r"(a[2]), "r"(a[3]), "r"(b0), "r"(b1));
}

// ---------------- conversion kernels (fp32 -> fp16) ----------------
__global__ void conv_x(const float* __restrict__ x) {
    size_t i = (size_t)blockIdx.x * blockDim.x + threadIdx.x;
    if (i >= (size_t)TSEQ * BH) return;
    g_x16[i] = __float2half(x[i]);
}
__global__ void conv_w(const float* __restrict__ Wih, const float* __restrict__ Whh) {
    size_t i = (size_t)blockIdx.x * blockDim.x + threadIdx.x;
    if (i >= (size_t)NLAY * HID * KTOT) return;
    int k = (int)(i & (KTOT - 1));
    size_t ln = i >> 11;                          // layer*HID + n
    float v = (k < HID) ? Wih[ln * HID + k] : Whh[ln * HID + (k - HID)];
    g_w16[i] = __float2half(v);
}

// ---------------- wavefront kernel ----------------
// 128 threads, 4 warps, warp-tile 32x32, CTA tile 64x64.
// Single-pass fp16 x fp16 -> fp32 HMMA; 5-stage cp.async pipeline (4-chunk lookahead).
__global__ void __launch_bounds__(128, 1)
rnn_wave_f16(int s, const float* __restrict__ bih, const float* __restrict__ bhh,
             float* __restrict__ out)
{
    const int layer = blockIdx.y;
    const int t = s - layer;
    if (t < 0 || t >= TSEQ) return;

    const int mt = blockIdx.x >> 4;        // 0..1
    const int nt = blockIdx.x & 15;        // 0..15
    const int m0 = mt * 64;
    const int n0 = nt * 64;

    extern __shared__ __align__(16) char dynsm[];
    const unsigned dbase = (smem_u32(dynsm) + 127) & ~127u;

    const int tid  = threadIdx.x;
    const int wid  = tid >> 5;
    const int lane = tid & 31;
    const int wm   = wid >> 1;             // warp M offset 32*wm
    const int wn   = wid & 1;              // warp N offset 32*wn

    // ---- source pointers ----
    const __half* cur = (layer == 0) ? g_x16 + (size_t)t * BH
                                     : g_r16 + (size_t)((layer-1)*2 + (t & 1)) * BH;
    const __half* hprev = g_r16 + (size_t)(layer*2 + ((t-1) & 1)) * BH;
    const __half* w = g_w16 + (size_t)layer * HID * KTOT;

    const int nChunks = (t == 0) ? (NCH / 2) : NCH;   // KC=128 divides HID: no straddle

    // ---- producer: 128 threads; per chunk: A 1024 granules + W 1024 -> 16 cp/thread ----
    const int prow = tid >> 3;             // 0..15
    const int pg   = tid & 7;
    const unsigned so0 = (unsigned)(prow*128 + ((pg ^ (prow & 7)) << 4));

    auto issue_chunk = [&](int c, int buf) {
        const unsigned sb = dbase + buf * STAGEB;
        const int k0 = c * KC;
        const __half* asrc; int koff;
        if (k0 < HID) { asrc = cur;   koff = k0; }
        else          { asrc = hprev; koff = k0 - HID; }
        #pragma unroll
        for (int sub = 0; sub < 2; sub++) {
            const unsigned sa = sb + sub * SUBB;            // A sub-tile
            const unsigned sw = sb + TILEB + sub * SUBB;    // W sub-tile
            const int ks = koff + sub * 64;
            const int kw = k0 + sub * 64;
            #pragma unroll
            for (int i = 0; i < 4; i++) {
                const int row = prow + 16*i;
                const unsigned so = so0 + 2048u*i;
                cp_async16(sa + so, asrc + (size_t)(m0+row)*HID + ks + pg*8);
                cp_async16(sw + so, w    + (size_t)(n0+row)*KTOT + kw + pg*8);
            }
        }
        cp_commit();
    };

    // ---- ldmatrix lane addressing ----
    const int x7 = lane & 7;
    const int asel = lane >> 4;
    const unsigned aRowOff0 = (unsigned)((wm*32 +      (lane & 15)) * 128);
    const unsigned aRowOff1 = (unsigned)((wm*32 + 16 + (lane & 15)) * 128);
    const int brow_in = (lane & 7) + ((lane & 16) >> 1);
    const int bsel = (lane >> 3) & 1;
    const unsigned bRowOff0 = (unsigned)((wn*32 +      brow_in) * 128);
    const unsigned bRowOff1 = (unsigned)((wn*32 + 16 + brow_in) * 128);

    float4 acc[2][4];
    #pragma unroll
    for (int mi = 0; mi < 2; mi++)
        #pragma unroll
        for (int nf = 0; nf < 4; nf++) acc[mi][nf] = make_float4(0.f, 0.f, 0.f, 0.f);

    // one k16 step: 4 LDSM + 8 MMA; processed in pairs so 8 LDSM are in flight together
    auto compute_chunk = [&](int buf) {
        const unsigned sb = dbase + buf * STAGEB;
        #pragma unroll
        for (int kp = 0; kp < 4; kp++) {               // pairs of k16 steps (8 total)
            unsigned a[2][2][4], b[2][2][4];
            #pragma unroll
            for (int u = 0; u < 2; u++) {
                const int kk = kp*2 + u;
                const unsigned ss = sb + (unsigned)(kk >> 2) * SUBB;
                const int ki = kk & 3;
                const unsigned axor = (unsigned)(((ki*2 + asel) ^ x7) << 4);
                const unsigned bxor = (unsigned)(((ki*2 + bsel) ^ x7) << 4);
                ldsm4(a[u][0][0], a[u][0][1], a[u][0][2], a[u][0][3], ss + aRowOff0 + axor);
                ldsm4(a[u][1][0], a[u][1][1], a[u][1][2], a[u][1][3], ss + aRowOff1 + axor);
                ldsm4(b[u][0][0], b[u][0][1], b[u][0][2], b[u][0][3], ss + TILEB + bRowOff0 + bxor);
                ldsm4(b[u][1][0], b[u][1][1], b[u][1][2], b[u][1][3], ss + TILEB + bRowOff1 + bxor);
            }
            #pragma unroll
            for (int u = 0; u < 2; u++)
                #pragma unroll
                for (int mi = 0; mi < 2; mi++)
                    #pragma unroll
                    for (int nf = 0; nf < 4; nf++)
                        mma16816(acc[mi][nf], a[u][mi],
                                 b[u][nf>>1][(nf&1)*2], b[u][nf>>1][(nf&1)*2+1]);
        }
    };

    // ---- 5-stage pipeline: 4-chunk lookahead, one barrier per chunk ----
    issue_chunk(0, 0);
    issue_chunk(1, 1);
    issue_chunk(2, 2);
    issue_chunk(3, 3);
    for (int c = 0; c < nChunks; c++) {
        if      (c + 3 < nChunks) cp_wait<3>();   // chunk c landed; c+1..c+3 may be in flight
        else if (c + 2 < nChunks) cp_wait<2>();
        else if (c + 1 < nChunks) cp_wait<1>();
        else                      cp_wait<0>();
        __syncthreads();          // chunk c visible; stage (c+4)%5 free (compute c-1 done)
        if (c + 4 < nChunks) issue_chunk(c + 4, (c + 4) % STAGES);
        compute_chunk(c % STAGES);
    }

    // ---- epilogue: bias + tanh, fp16 to ring, fp32 to out for top layer ----
    const size_t rb = (size_t)(layer*2 + (t & 1)) * BH;
    #pragma unroll
    for (int mi = 0; mi < 2; mi++) {
        const int mlo = m0 + wm*32 + mi*16 + (lane >> 2);
        #pragma unroll
        for (int nf = 0; nf < 4; nf++) {
            const int n = n0 + wn*32 + nf*8 + (lane & 3)*2;
            const float b0 = bih[layer*HID + n]     + bhh[layer*HID + n];
            const float b1 = bih[layer*HID + n + 1] + bhh[layer*HID + n + 1];
            const float v00 = tanhf(acc[mi][nf].x + b0);
            const float v01 = tanhf(acc[mi][nf].y + b1);
            const float v10 = tanhf(acc[mi][nf].z + b0);
            const float v11 = tanhf(acc[mi][nf].w + b1);
            #pragma unroll
            for (int rh = 0; rh < 2; rh++) {
                const int m = mlo + rh*8;
                const float va = rh ? v10 : v00;
                const float vb = rh ? v11 : v01;
                const __half ha = __float2half(va);
                const __half hb = __float2half(vb);
                const unsigned hpack = (unsigned)__half_as_ushort(ha) |
                                       ((unsigned)__half_as_ushort(hb) << 16);
                *reinterpret_cast<unsigned*>(&g_r16[rb + (size_t)m*HID + n]) = hpack;
                if (layer == NLAY - 1) {
                    float2 o = make_float2(va, vb);
                    *reinterpret_cast<float2*>(&out[(size_t)t*BH + (size_t)m*HID + n]) = o;
                }
            }
        }
    }
}

extern "C" void kernel_launch(void* const* d_in, const int* in_sizes, int n_in,
                              void* d_out, int out_size) {
    const float* x   = (const float*)d_in[0];
    const float* Wih = (const float*)d_in[1];
    const float* Whh = (const float*)d_in[2];
    const float* bih = (const float*)d_in[3];
    const float* bhh = (const float*)d_in[4];
    float* out = (float*)d_out;

    cudaFuncSetAttribute(rnn_wave_f16, cudaFuncAttributeMaxDynamicSharedMemorySize, DYN_SMEM);

    // One-time (per replay) fp32 -> fp16 conversion
    conv_x<<<(unsigned)(((size_t)TSEQ*BH + 255) / 256), 256>>>(x);
    conv_w<<<(unsigned)(((size_t)NLAY*HID*KTOT + 255) / 256), 256>>>(Wih, Whh);

    // Wavefront s = t + layer: 515 sequential launches; kernel boundaries = sync.
    const dim3 grid(32, NLAY);
    for (int s = 0; s < TSEQ + NLAY - 1; s++) {
        rnn_wave_f16<<<grid, 128, DYN_SMEM>>>(s, bih, bhh, out);
    }
}